// round 2
// baseline (speedup 1.0000x reference)
#include <cuda_runtime.h>
#include <cuda_bf16.h>

// PositionalEncoding via angle-addition recurrence.
// out[pos, 2i]   = sin(pos * w_i),  out[pos, 2i+1] = cos(pos * w_i),
// w_i = 10000^{-i/512}, d_model = 1024, seq_len = out_size / 1024.
// Input X is shape-only (unused).
//
// R1: previous version was issue-bound on accurate sincosf (~30 instrs/elem,
// issue=82.6%, alu=36.6%). Replace per-element sincosf with a 2D rotation:
// each block owns a contiguous 16-row chunk; each thread seeds (s,c) once
// with accurate sincosf, then rotates by w per row (4 FMA/elem). Each thread
// handles TWO adjacent pair-columns -> one float4 (STG.128) per row.
// Error: ~16 steps of few-ulp rotation error, < 1e-6 abs. New limiter: L2
// store bandwidth (~3us floor for 33.5MB) + seed cost.

#define D_MODEL 1024
#define D_HALF  (D_MODEL / 2)          // 512 pairs per row
#define THREADS 256                    // each thread: 2 pairs -> 1 float4
#define ROWS_PER_BLOCK 16

__global__ __launch_bounds__(THREADS, 8)
void pe_kernel(float4* __restrict__ out, int seq_len) {
    const int t  = threadIdx.x;        // 0..255
    const int i0 = 2 * t;              // pair indices this thread owns
    const int i1 = 2 * t + 1;

    // inverse frequencies: 10000^{-i/512}
    const float inv = 1.0f / (float)D_HALF;
    const float w0 = powf(10000.0f, -(float)i0 * inv);
    const float w1 = powf(10000.0f, -(float)i1 * inv);

    const int row0 = blockIdx.x * ROWS_PER_BLOCK;
    if (row0 >= seq_len) return;

    // Seed: accurate sincos of the chunk-start angle and of the per-row step.
    float s0, c0, s1, c1, sw0, cw0, sw1, cw1;
    sincosf((float)row0 * w0, &s0, &c0);
    sincosf((float)row0 * w1, &s1, &c1);
    sincosf(w0, &sw0, &cw0);
    sincosf(w1, &sw1, &cw1);

    // Row stride in float4 units: 1024 floats = 256 float4.
    float4* p = out + (size_t)row0 * (D_MODEL / 4) + t;

    const int rows = min(ROWS_PER_BLOCK, seq_len - row0);
    #pragma unroll
    for (int r = 0; r < ROWS_PER_BLOCK; r++) {
        if (r < rows) {
            *p = make_float4(s0, c0, s1, c1);
            p += (D_MODEL / 4);
            // rotate by w: (s,c) <- (s*cw + c*sw, c*cw - s*sw)
            float ns0 = fmaf(s0, cw0,  c0 * sw0);
            float nc0 = fmaf(c0, cw0, -s0 * sw0);
            float ns1 = fmaf(s1, cw1,  c1 * sw1);
            float nc1 = fmaf(c1, cw1, -s1 * sw1);
            s0 = ns0; c0 = nc0; s1 = ns1; c1 = nc1;
        }
    }
}

extern "C" void kernel_launch(void* const* d_in, const int* in_sizes, int n_in,
                              void* d_out, int out_size) {
    (void)d_in; (void)in_sizes; (void)n_in;
    const int seq_len = out_size / D_MODEL;    // 8192
    float4* out = (float4*)d_out;

    const int grid = (seq_len + ROWS_PER_BLOCK - 1) / ROWS_PER_BLOCK;  // 512
    pe_kernel<<<grid, THREADS>>>(out, seq_len);
}